// round 1
// baseline (speedup 1.0000x reference)
#include <cuda_runtime.h>
#include <math.h>

// Problem constants
#define NB 2
#define NS 2048
#define NE 1024
#define NH 16
#define ND 64
#define NM (NB*NS)   // 4096 rows

// ---------------- scratch (static device globals; no allocation) -------------
__device__ float g_q[NB*NH*NS*ND];    // [B,H,S,D] roped, pre-scaled by 1/sqrt(D)
__device__ float g_k[NB*NH*NS*ND];    // [B,H,S,D] roped
__device__ float g_v[NB*NH*NS*ND];    // [B,H,S,D]
__device__ float g_att[NB*NS*NE];     // [B,S,H,D] == [B,S,E]
__device__ float g_invfreq[ND/2];

// inv_freq computed in double so fp32 rounding matches reference to ~1 ulp
__global__ void init_invfreq_kernel() {
    int i = threadIdx.x;
    if (i < ND/2) {
        double ex = (double)(2*i) / (double)ND;           // 2i/D
        // 10000^(-ex) = 2^(-ex*log2(10000))
        g_invfreq[i] = (float)exp2(-ex * 13.287712379549449);
    }
}

// Fast FMA-only exp (x <= 0 path in softmax). Rel err ~2e-7.
__device__ __forceinline__ float fexp(float x) {
    x = fmaxf(x, -87.0f);
    float y = x * 1.4426950408889634f;   // x * log2(e)
    float n = rintf(y);
    float f = y - n;                     // |f| <= 0.5
    // 2^f, degree-6 Taylor in f (coeffs (ln2)^k/k!)
    float p =            1.5403530e-4f;
    p = fmaf(p, f, 1.3333558e-3f);
    p = fmaf(p, f, 9.6181291e-3f);
    p = fmaf(p, f, 5.5504109e-2f);
    p = fmaf(p, f, 2.4022651e-1f);
    p = fmaf(p, f, 6.9314718e-1f);
    p = fmaf(p, f, 1.0f);
    int ei = (int)n;                     // n in [-126, ~128]
    float sc = __int_as_float((ei + 127) << 23);
    return p * sc;
}

// ---------------- GEMM: C[m,n] = sum_k A[m,k]*Wt[n,k] + bias[n] --------------
// BM=BN=128, BK=16, 256 threads, 8x8 per thread.
// MODE 0: A = g_att, plain write to Cout[M,E]         (output projection)
// MODE 1: A = Ain,  RoPE + 0.125 scale, scatter to g_q[B,H,S,D]
// MODE 2: A = Ain,  RoPE,                scatter to g_k
// MODE 3: A = Ain,  plain,               scatter to g_v
template<int MODE>
__global__ __launch_bounds__(256) void gemm_kernel(
    const float* __restrict__ Ain, const float* __restrict__ Wt,
    const float* __restrict__ bias, float* __restrict__ Cout)
{
    const float* A = (MODE == 0) ? (const float*)g_att : Ain;
    __shared__ float As[16][132];   // [k][m], padded (132*4 % 16 == 0, stride%32 = 4)
    __shared__ float Bs[16][132];   // [k][n]

    int tid = threadIdx.x;
    int m0 = blockIdx.y * 128;
    int n0 = blockIdx.x * 128;
    int tr = tid >> 4;       // 0..15
    int tc = tid & 15;       // 0..15

    float acc[8][8];
    #pragma unroll
    for (int i = 0; i < 8; i++)
        #pragma unroll
        for (int j = 0; j < 8; j++) acc[i][j] = 0.f;

    for (int kk = 0; kk < NE; kk += 16) {
        #pragma unroll
        for (int i = 0; i < 2; i++) {
            int idx = tid + i*256;        // 0..511 (float4 index)
            int row = idx >> 2;           // 0..127
            int k4  = (idx & 3) << 2;     // 0,4,8,12
            float4 a = *(const float4*)(A  + (size_t)(m0+row)*NE + kk + k4);
            As[k4+0][row]=a.x; As[k4+1][row]=a.y; As[k4+2][row]=a.z; As[k4+3][row]=a.w;
            float4 b = *(const float4*)(Wt + (size_t)(n0+row)*NE + kk + k4);
            Bs[k4+0][row]=b.x; Bs[k4+1][row]=b.y; Bs[k4+2][row]=b.z; Bs[k4+3][row]=b.w;
        }
        __syncthreads();
        #pragma unroll
        for (int k = 0; k < 16; k++) {
            float ra[8], rb[8];
            *(float4*)&ra[0] = *(float4*)&As[k][tr*8];
            *(float4*)&ra[4] = *(float4*)&As[k][tr*8+4];
            *(float4*)&rb[0] = *(float4*)&Bs[k][tc*8];
            *(float4*)&rb[4] = *(float4*)&Bs[k][tc*8+4];
            #pragma unroll
            for (int i = 0; i < 8; i++)
                #pragma unroll
                for (int j = 0; j < 8; j++)
                    acc[i][j] = fmaf(ra[i], rb[j], acc[i][j]);
        }
        __syncthreads();
    }

    if (MODE == 0) {
        #pragma unroll
        for (int i = 0; i < 8; i++) {
            int r = m0 + tr*8 + i;
            #pragma unroll
            for (int j = 0; j < 8; j += 4) {
                int c = n0 + tc*8 + j;
                float4 o;
                o.x = acc[i][j+0] + bias[c+0];
                o.y = acc[i][j+1] + bias[c+1];
                o.z = acc[i][j+2] + bias[c+2];
                o.w = acc[i][j+3] + bias[c+3];
                *(float4*)(Cout + (size_t)r*NE + c) = o;
            }
        }
    } else {
        float* dstbase = (MODE == 1) ? g_q : (MODE == 2) ? g_k : g_v;
        #pragma unroll
        for (int i = 0; i < 8; i++) {
            int r = m0 + tr*8 + i;
            int b = r >> 11;            // /S
            int s = r & (NS-1);
            #pragma unroll
            for (int jp = 0; jp < 4; jp++) {
                int c = n0 + tc*8 + jp*2;   // even
                int h = c >> 6;
                int d = c & 63;             // even
                float ve = acc[i][jp*2+0] + bias[c+0];
                float vo = acc[i][jp*2+1] + bias[c+1];
                float oe, oo;
                if (MODE == 3) {
                    oe = ve; oo = vo;
                } else {
                    float ang = (float)s * g_invfreq[d >> 1];
                    float sn, cs;
                    sincosf(ang, &sn, &cs);
                    oe = ve*cs - vo*sn;
                    oo = vo*cs + ve*sn;
                    if (MODE == 1) { oe *= 0.125f; oo *= 0.125f; }  // 1/sqrt(64)
                }
                float2 o2 = make_float2(oe, oo);
                *(float2*)(dstbase + ((size_t)((b*NH + h)*NS + s))*ND + d) = o2;
            }
        }
    }
}

// ---------------- Flash attention, fp32, one q-row per thread ----------------
// grid: (S/64, B*H), block 64 threads. K/V tiles of 64 rows in smem.
// All K/V smem addresses are warp-uniform -> broadcast LDS (1 wavefront each).
__global__ __launch_bounds__(64) void attn_kernel()
{
    __shared__ float Ks[64*64];
    __shared__ float Vs[64*64];
    int tid = threadIdx.x;
    int bh  = blockIdx.y;           // b*H + h
    int q0  = blockIdx.x * 64;

    const float* qbase = g_q + (size_t)bh * NS * ND;
    const float* kbase = g_k + (size_t)bh * NS * ND;
    const float* vbase = g_v + (size_t)bh * NS * ND;

    float q[64];
    #pragma unroll
    for (int t = 0; t < 16; t++)
        *(float4*)&q[t*4] = *(const float4*)(qbase + (size_t)(q0 + tid)*ND + t*4);

    float acc[64];
    #pragma unroll
    for (int d = 0; d < 64; d++) acc[d] = 0.f;
    float mrow = -INFINITY, lrow = 0.f;

    float4* ks4 = (float4*)Ks;
    float4* vs4 = (float4*)Vs;

    for (int kt = 0; kt < NS; kt += 64) {
        __syncthreads();
        const float4* kg = (const float4*)(kbase + (size_t)kt*ND);
        const float4* vg = (const float4*)(vbase + (size_t)kt*ND);
        #pragma unroll
        for (int it = 0; it < 16; it++) {
            ks4[it*64 + tid] = kg[it*64 + tid];
            vs4[it*64 + tid] = vg[it*64 + tid];
        }
        __syncthreads();

        #pragma unroll
        for (int jc = 0; jc < 4; jc++) {
            float sc[16];
            #pragma unroll
            for (int jj = 0; jj < 16; jj++) {
                int j = jc*16 + jj;
                float s0 = 0.f, s1 = 0.f, s2 = 0.f, s3 = 0.f;
                #pragma unroll
                for (int t = 0; t < 16; t++) {
                    float4 kv = ks4[j*16 + t];   // warp-uniform -> broadcast
                    s0 = fmaf(q[t*4+0], kv.x, s0);
                    s1 = fmaf(q[t*4+1], kv.y, s1);
                    s2 = fmaf(q[t*4+2], kv.z, s2);
                    s3 = fmaf(q[t*4+3], kv.w, s3);
                }
                sc[jj] = (s0 + s1) + (s2 + s3);
            }
            float mc = sc[0];
            #pragma unroll
            for (int jj = 1; jj < 16; jj++) mc = fmaxf(mc, sc[jj]);
            float mnew = fmaxf(mrow, mc);
            float corr = fexp(mrow - mnew);
            lrow *= corr;
            #pragma unroll
            for (int d = 0; d < 64; d++) acc[d] *= corr;
            #pragma unroll
            for (int jj = 0; jj < 16; jj++) {
                int j = jc*16 + jj;
                float p = fexp(sc[jj] - mnew);
                lrow += p;
                #pragma unroll
                for (int t = 0; t < 16; t++) {
                    float4 vv = vs4[j*16 + t];   // warp-uniform -> broadcast
                    acc[t*4+0] = fmaf(p, vv.x, acc[t*4+0]);
                    acc[t*4+1] = fmaf(p, vv.y, acc[t*4+1]);
                    acc[t*4+2] = fmaf(p, vv.z, acc[t*4+2]);
                    acc[t*4+3] = fmaf(p, vv.w, acc[t*4+3]);
                }
            }
            mrow = mnew;
        }
    }

    float inv = 1.0f / lrow;
    int b = bh >> 4, h = bh & 15;
    // write [B,S,H,D] == [B,S,E] so the O-projection reads row-major
    float* dst = g_att + ((size_t)(b*NS + q0 + tid) * NH + h) * ND;
    #pragma unroll
    for (int t = 0; t < 16; t++) {
        float4 o;
        o.x = acc[t*4+0] * inv;
        o.y = acc[t*4+1] * inv;
        o.z = acc[t*4+2] * inv;
        o.w = acc[t*4+3] * inv;
        *(float4*)(dst + t*4) = o;
    }
}

// ------------------------------- launch --------------------------------------
extern "C" void kernel_launch(void* const* d_in, const int* in_sizes, int n_in,
                              void* d_out, int out_size)
{
    const float* query = (const float*)d_in[0];
    const float* key   = (const float*)d_in[1];
    const float* value = (const float*)d_in[2];
    const float* Wq    = (const float*)d_in[3];
    const float* bq    = (const float*)d_in[4];
    const float* Wk    = (const float*)d_in[5];
    const float* bk    = (const float*)d_in[6];
    const float* Wv    = (const float*)d_in[7];
    const float* bv    = (const float*)d_in[8];
    const float* Wo    = (const float*)d_in[9];
    const float* bo    = (const float*)d_in[10];
    float* out = (float*)d_out;

    dim3 ggrid(NE/128, NM/128);   // (8, 32)

    init_invfreq_kernel<<<1, 32>>>();
    gemm_kernel<1><<<ggrid, 256>>>(query, Wq, bq, nullptr);
    gemm_kernel<2><<<ggrid, 256>>>(key,   Wk, bk, nullptr);
    gemm_kernel<3><<<ggrid, 256>>>(value, Wv, bv, nullptr);
    attn_kernel<<<dim3(NS/64, NB*NH), 64>>>();
    gemm_kernel<0><<<ggrid, 256>>>(nullptr, Wo, bo, out);
}

// round 2
// speedup vs baseline: 1.0012x; 1.0012x over previous
#include <cuda_runtime.h>
#include <math.h>

// Problem constants
#define NB 2
#define NS 2048
#define NE 1024
#define NH 16
#define ND 64
#define NM (NB*NS)   // 4096 rows

// ---------------- scratch (static device globals; no allocation) -------------
__device__ float g_q[NB*NH*NS*ND];    // [B,H,S,D] roped, pre-scaled by 1/sqrt(D)
__device__ float g_k[NB*NH*NS*ND];    // [B,H,S,D] roped
__device__ float g_v[NB*NH*NS*ND];    // [B,H,S,D]
__device__ float g_att[NB*NS*NE];     // [B,S,H,D] == [B,S,E]
__device__ float g_invfreq[ND/2];

// inv_freq computed in double so fp32 rounding matches reference to ~1 ulp
__global__ void init_invfreq_kernel() {
    int i = threadIdx.x;
    if (i < ND/2) {
        double ex = (double)(2*i) / (double)ND;           // 2i/D
        // 10000^(-ex) = 2^(-ex*log2(10000))
        g_invfreq[i] = (float)exp2(-ex * 13.287712379549449);
    }
}

// Fast FMA-only exp (x <= 0 path in softmax). Rel err ~2e-7.
__device__ __forceinline__ float fexp(float x) {
    x = fmaxf(x, -87.0f);
    float y = x * 1.4426950408889634f;   // x * log2(e)
    float n = rintf(y);
    float f = y - n;                     // |f| <= 0.5
    // 2^f, degree-6 Taylor in f (coeffs (ln2)^k/k!)
    float p =            1.5403530e-4f;
    p = fmaf(p, f, 1.3333558e-3f);
    p = fmaf(p, f, 9.6181291e-3f);
    p = fmaf(p, f, 5.5504109e-2f);
    p = fmaf(p, f, 2.4022651e-1f);
    p = fmaf(p, f, 6.9314718e-1f);
    p = fmaf(p, f, 1.0f);
    int ei = (int)n;                     // n in [-126, ~128]
    float sc = __int_as_float((ei + 127) << 23);
    return p * sc;
}

// ---------------- GEMM: C[m,n] = sum_k A[m,k]*Wt[n,k] + bias[n] --------------
// BM=BN=128, BK=16, 256 threads, 8x8 per thread.
// MODE 0: A = g_att, plain write to Cout[M,E]         (output projection)
// MODE 1: A = Ain,  RoPE + 0.125 scale, scatter to g_q[B,H,S,D]
// MODE 2: A = Ain,  RoPE,                scatter to g_k
// MODE 3: A = Ain,  plain,               scatter to g_v
template<int MODE>
__global__ __launch_bounds__(256) void gemm_kernel(
    const float* __restrict__ Ain, const float* __restrict__ Wt,
    const float* __restrict__ bias, float* __restrict__ Cout)
{
    const float* A = (MODE == 0) ? (const float*)g_att : Ain;
    __shared__ float As[16][132];   // [k][m], padded (132*4 % 16 == 0, stride%32 = 4)
    __shared__ float Bs[16][132];   // [k][n]

    int tid = threadIdx.x;
    int m0 = blockIdx.y * 128;
    int n0 = blockIdx.x * 128;
    int tr = tid >> 4;       // 0..15
    int tc = tid & 15;       // 0..15

    float acc[8][8];
    #pragma unroll
    for (int i = 0; i < 8; i++)
        #pragma unroll
        for (int j = 0; j < 8; j++) acc[i][j] = 0.f;

    for (int kk = 0; kk < NE; kk += 16) {
        #pragma unroll
        for (int i = 0; i < 2; i++) {
            int idx = tid + i*256;        // 0..511 (float4 index)
            int row = idx >> 2;           // 0..127
            int k4  = (idx & 3) << 2;     // 0,4,8,12
            float4 a = *(const float4*)(A  + (size_t)(m0+row)*NE + kk + k4);
            As[k4+0][row]=a.x; As[k4+1][row]=a.y; As[k4+2][row]=a.z; As[k4+3][row]=a.w;
            float4 b = *(const float4*)(Wt + (size_t)(n0+row)*NE + kk + k4);
            Bs[k4+0][row]=b.x; Bs[k4+1][row]=b.y; Bs[k4+2][row]=b.z; Bs[k4+3][row]=b.w;
        }
        __syncthreads();
        #pragma unroll
        for (int k = 0; k < 16; k++) {
            float ra[8], rb[8];
            *(float4*)&ra[0] = *(float4*)&As[k][tr*8];
            *(float4*)&ra[4] = *(float4*)&As[k][tr*8+4];
            *(float4*)&rb[0] = *(float4*)&Bs[k][tc*8];
            *(float4*)&rb[4] = *(float4*)&Bs[k][tc*8+4];
            #pragma unroll
            for (int i = 0; i < 8; i++)
                #pragma unroll
                for (int j = 0; j < 8; j++)
                    acc[i][j] = fmaf(ra[i], rb[j], acc[i][j]);
        }
        __syncthreads();
    }

    if (MODE == 0) {
        #pragma unroll
        for (int i = 0; i < 8; i++) {
            int r = m0 + tr*8 + i;
            #pragma unroll
            for (int j = 0; j < 8; j += 4) {
                int c = n0 + tc*8 + j;
                float4 o;
                o.x = acc[i][j+0] + bias[c+0];
                o.y = acc[i][j+1] + bias[c+1];
                o.z = acc[i][j+2] + bias[c+2];
                o.w = acc[i][j+3] + bias[c+3];
                *(float4*)(Cout + (size_t)r*NE + c) = o;
            }
        }
    } else {
        float* dstbase = (MODE == 1) ? g_q : (MODE == 2) ? g_k : g_v;
        #pragma unroll
        for (int i = 0; i < 8; i++) {
            int r = m0 + tr*8 + i;
            int b = r >> 11;            // /S
            int s = r & (NS-1);
            #pragma unroll
            for (int jp = 0; jp < 4; jp++) {
                int c = n0 + tc*8 + jp*2;   // even
                int h = c >> 6;
                int d = c & 63;             // even
                float ve = acc[i][jp*2+0] + bias[c+0];
                float vo = acc[i][jp*2+1] + bias[c+1];
                float oe, oo;
                if (MODE == 3) {
                    oe = ve; oo = vo;
                } else {
                    float ang = (float)s * g_invfreq[d >> 1];
                    float sn, cs;
                    sincosf(ang, &sn, &cs);
                    oe = ve*cs - vo*sn;
                    oo = vo*cs + ve*sn;
                    if (MODE == 1) { oe *= 0.125f; oo *= 0.125f; }  // 1/sqrt(64)
                }
                float2 o2 = make_float2(oe, oo);
                *(float2*)(dstbase + ((size_t)((b*NH + h)*NS + s))*ND + d) = o2;
            }
        }
    }
}

// ---------------- Flash attention, fp32, one q-row per thread ----------------
// grid: (S/64, B*H), block 64 threads. K/V tiles of 64 rows in smem.
// All K/V smem addresses are warp-uniform -> broadcast LDS (1 wavefront each).
__global__ __launch_bounds__(64) void attn_kernel()
{
    __shared__ float Ks[64*64];
    __shared__ float Vs[64*64];
    int tid = threadIdx.x;
    int bh  = blockIdx.y;           // b*H + h
    int q0  = blockIdx.x * 64;

    const float* qbase = g_q + (size_t)bh * NS * ND;
    const float* kbase = g_k + (size_t)bh * NS * ND;
    const float* vbase = g_v + (size_t)bh * NS * ND;

    float q[64];
    #pragma unroll
    for (int t = 0; t < 16; t++)
        *(float4*)&q[t*4] = *(const float4*)(qbase + (size_t)(q0 + tid)*ND + t*4);

    float acc[64];
    #pragma unroll
    for (int d = 0; d < 64; d++) acc[d] = 0.f;
    float mrow = -INFINITY, lrow = 0.f;

    float4* ks4 = (float4*)Ks;
    float4* vs4 = (float4*)Vs;

    for (int kt = 0; kt < NS; kt += 64) {
        __syncthreads();
        const float4* kg = (const float4*)(kbase + (size_t)kt*ND);
        const float4* vg = (const float4*)(vbase + (size_t)kt*ND);
        #pragma unroll
        for (int it = 0; it < 16; it++) {
            ks4[it*64 + tid] = kg[it*64 + tid];
            vs4[it*64 + tid] = vg[it*64 + tid];
        }
        __syncthreads();

        #pragma unroll
        for (int jc = 0; jc < 4; jc++) {
            float sc[16];
            #pragma unroll
            for (int jj = 0; jj < 16; jj++) {
                int j = jc*16 + jj;
                float s0 = 0.f, s1 = 0.f, s2 = 0.f, s3 = 0.f;
                #pragma unroll
                for (int t = 0; t < 16; t++) {
                    float4 kv = ks4[j*16 + t];   // warp-uniform -> broadcast
                    s0 = fmaf(q[t*4+0], kv.x, s0);
                    s1 = fmaf(q[t*4+1], kv.y, s1);
                    s2 = fmaf(q[t*4+2], kv.z, s2);
                    s3 = fmaf(q[t*4+3], kv.w, s3);
                }
                sc[jj] = (s0 + s1) + (s2 + s3);
            }
            float mc = sc[0];
            #pragma unroll
            for (int jj = 1; jj < 16; jj++) mc = fmaxf(mc, sc[jj]);
            float mnew = fmaxf(mrow, mc);
            float corr = fexp(mrow - mnew);
            lrow *= corr;
            #pragma unroll
            for (int d = 0; d < 64; d++) acc[d] *= corr;
            #pragma unroll
            for (int jj = 0; jj < 16; jj++) {
                int j = jc*16 + jj;
                float p = fexp(sc[jj] - mnew);
                lrow += p;
                #pragma unroll
                for (int t = 0; t < 16; t++) {
                    float4 vv = vs4[j*16 + t];   // warp-uniform -> broadcast
                    acc[t*4+0] = fmaf(p, vv.x, acc[t*4+0]);
                    acc[t*4+1] = fmaf(p, vv.y, acc[t*4+1]);
                    acc[t*4+2] = fmaf(p, vv.z, acc[t*4+2]);
                    acc[t*4+3] = fmaf(p, vv.w, acc[t*4+3]);
                }
            }
            mrow = mnew;
        }
    }

    float inv = 1.0f / lrow;
    int b = bh >> 4, h = bh & 15;
    // write [B,S,H,D] == [B,S,E] so the O-projection reads row-major
    float* dst = g_att + ((size_t)(b*NS + q0 + tid) * NH + h) * ND;
    #pragma unroll
    for (int t = 0; t < 16; t++) {
        float4 o;
        o.x = acc[t*4+0] * inv;
        o.y = acc[t*4+1] * inv;
        o.z = acc[t*4+2] * inv;
        o.w = acc[t*4+3] * inv;
        *(float4*)(dst + t*4) = o;
    }
}

// ------------------------------- launch --------------------------------------
extern "C" void kernel_launch(void* const* d_in, const int* in_sizes, int n_in,
                              void* d_out, int out_size)
{
    const float* query = (const float*)d_in[0];
    const float* key   = (const float*)d_in[1];
    const float* value = (const float*)d_in[2];
    const float* Wq    = (const float*)d_in[3];
    const float* bq    = (const float*)d_in[4];
    const float* Wk    = (const float*)d_in[5];
    const float* bk    = (const float*)d_in[6];
    const float* Wv    = (const float*)d_in[7];
    const float* bv    = (const float*)d_in[8];
    const float* Wo    = (const float*)d_in[9];
    const float* bo    = (const float*)d_in[10];
    float* out = (float*)d_out;

    dim3 ggrid(NE/128, NM/128);   // (8, 32)

    init_invfreq_kernel<<<1, 32>>>();
    gemm_kernel<1><<<ggrid, 256>>>(query, Wq, bq, nullptr);
    gemm_kernel<2><<<ggrid, 256>>>(key,   Wk, bk, nullptr);
    gemm_kernel<3><<<ggrid, 256>>>(value, Wv, bv, nullptr);
    attn_kernel<<<dim3(NS/64, NB*NH), 64>>>();
    gemm_kernel<0><<<ggrid, 256>>>(nullptr, Wo, bo, out);
}

// round 3
// speedup vs baseline: 5.1774x; 5.1713x over previous
#include <cuda_runtime.h>
#include <math.h>

// Problem constants
#define NB 2
#define NS 2048
#define NE 1024
#define NH 16
#define ND 64
#define NM (NB*NS)   // 4096 rows

// ---------------- scratch (static device globals; no allocation) -------------
__device__ float g_q[NB*NH*NS*ND];    // [B,H,S,D] roped, pre-scaled by 1/sqrt(D)
__device__ float g_k[NB*NH*NS*ND];    // [B,H,S,D] roped
__device__ float g_v[NB*NH*NS*ND];    // [B,H,S,D]
__device__ float g_att[NB*NS*NE];     // [B,S,H,D] == [B,S,E]
__device__ float g_invfreq[ND/2];

__global__ void init_invfreq_kernel() {
    int i = threadIdx.x;
    if (i < ND/2) {
        double ex = (double)(2*i) / (double)ND;
        g_invfreq[i] = (float)exp2(-ex * 13.287712379549449); // 10000^(-2i/D)
    }
}

// ---------------- tf32 helpers ------------------------------------------------
__device__ __forceinline__ unsigned f2tf(float x) {
    unsigned u;
    asm("cvt.rna.tf32.f32 %0, %1;" : "=r"(u) : "f"(x));
    return u;
}

__device__ __forceinline__ void mma_tf32(float c[4], const unsigned a[4], const unsigned b[2]) {
    asm volatile(
        "mma.sync.aligned.m16n8k8.row.col.f32.tf32.tf32.f32 "
        "{%0,%1,%2,%3}, {%4,%5,%6,%7}, {%8,%9}, {%0,%1,%2,%3};"
        : "+f"(c[0]), "+f"(c[1]), "+f"(c[2]), "+f"(c[3])
        : "r"(a[0]), "r"(a[1]), "r"(a[2]), "r"(a[3]),
          "r"(b[0]), "r"(b[1]));
}

// ---------------- GEMM: C[m,n] = sum_k A[m,k]*Wt[n,k] + bias[n] --------------
// BM=128, BN=128, BK=32. 256 threads = 8 warps (2 m-warps x 4 n-warps).
// Warp tile 64x32 = 4x4 grid of m16n8 mma tiles.
// MODE 0: A = g_att, plain write to Cout[M,E]         (output projection)
// MODE 1: A = Ain,  RoPE + 0.125 scale, scatter to g_q[B,H,S,D]
// MODE 2: A = Ain,  RoPE,                scatter to g_k
// MODE 3: A = Ain,  plain,               scatter to g_v
#define ASTR 36   // 36 % 32 == 4 -> conflict-free fragment loads
template<int MODE>
__global__ __launch_bounds__(256) void gemm_tc(
    const float* __restrict__ Ain, const float* __restrict__ Wt,
    const float* __restrict__ bias, float* __restrict__ Cout)
{
    const float* A = (MODE == 0) ? (const float*)g_att : Ain;
    __shared__ unsigned As[128*ASTR];
    __shared__ unsigned Bs[128*ASTR];

    int tid  = threadIdx.x;
    int lane = tid & 31, wid = tid >> 5;
    int wm = wid & 1, wn = wid >> 1;
    int g = lane >> 2, tg = lane & 3;
    int m0 = blockIdx.y * 128;
    int n0 = blockIdx.x * 128;

    float c[4][4][4];
    #pragma unroll
    for (int mt = 0; mt < 4; mt++)
        #pragma unroll
        for (int nt = 0; nt < 4; nt++)
            #pragma unroll
            for (int j = 0; j < 4; j++) c[mt][nt][j] = 0.f;

    for (int kk = 0; kk < NE; kk += 32) {
        #pragma unroll
        for (int i = 0; i < 4; i++) {
            int f4  = tid + i*256;          // 0..1023
            int row = f4 >> 3;              // 0..127
            int kc  = (f4 & 7) << 2;        // 0..28
            float4 av = *(const float4*)(A  + (size_t)(m0+row)*NE + kk + kc);
            uint4 at = make_uint4(f2tf(av.x), f2tf(av.y), f2tf(av.z), f2tf(av.w));
            *(uint4*)&As[row*ASTR + kc] = at;
            float4 bv = *(const float4*)(Wt + (size_t)(n0+row)*NE + kk + kc);
            uint4 bt = make_uint4(f2tf(bv.x), f2tf(bv.y), f2tf(bv.z), f2tf(bv.w));
            *(uint4*)&Bs[row*ASTR + kc] = bt;
        }
        __syncthreads();
        #pragma unroll
        for (int ks = 0; ks < 4; ks++) {
            unsigned a[4][4], b[4][2];
            int cidx = ks*8 + tg;
            #pragma unroll
            for (int mt = 0; mt < 4; mt++) {
                int r = wm*64 + mt*16 + g;
                a[mt][0] = As[r*ASTR + cidx];
                a[mt][1] = As[(r+8)*ASTR + cidx];
                a[mt][2] = As[r*ASTR + cidx + 4];
                a[mt][3] = As[(r+8)*ASTR + cidx + 4];
            }
            #pragma unroll
            for (int nt = 0; nt < 4; nt++) {
                int n = wn*32 + nt*8 + g;
                b[nt][0] = Bs[n*ASTR + cidx];
                b[nt][1] = Bs[n*ASTR + cidx + 4];
            }
            #pragma unroll
            for (int mt = 0; mt < 4; mt++)
                #pragma unroll
                for (int nt = 0; nt < 4; nt++)
                    mma_tf32(c[mt][nt], a[mt], b[nt]);
        }
        __syncthreads();
    }

    // Epilogue. Each thread holds, per (mt,nt) tile:
    //   (row0, col), (row0, col+1), (row0+8, col), (row0+8, col+1)
    // with col even -> perfect RoPE even/odd pairing.
    #pragma unroll
    for (int mt = 0; mt < 4; mt++) {
        int r0 = m0 + wm*64 + mt*16 + g;
        #pragma unroll
        for (int nt = 0; nt < 4; nt++) {
            int col = n0 + wn*32 + nt*8 + 2*tg;
            float b0 = bias[col], b1 = bias[col+1];
            float v00 = c[mt][nt][0] + b0, v01 = c[mt][nt][1] + b1;  // row r0
            float v10 = c[mt][nt][2] + b0, v11 = c[mt][nt][3] + b1;  // row r0+8
            if (MODE == 0) {
                *(float2*)(Cout + (size_t)r0*NE + col)     = make_float2(v00, v01);
                *(float2*)(Cout + (size_t)(r0+8)*NE + col) = make_float2(v10, v11);
            } else {
                float* dstbase = (MODE == 1) ? g_q : (MODE == 2) ? g_k : g_v;
                int h = col >> 6;
                int d = col & 63;               // even
                #pragma unroll
                for (int rr = 0; rr < 2; rr++) {
                    int r = r0 + rr*8;
                    int b = r >> 11;            // / NS
                    int s = r & (NS-1);
                    float ve = rr ? v10 : v00;
                    float vo = rr ? v11 : v01;
                    float oe, oo;
                    if (MODE == 3) {
                        oe = ve; oo = vo;
                    } else {
                        float ang = (float)s * g_invfreq[d >> 1];
                        float sn, cs;
                        sincosf(ang, &sn, &cs);
                        oe = ve*cs - vo*sn;
                        oo = vo*cs + ve*sn;
                        if (MODE == 1) { oe *= 0.125f; oo *= 0.125f; }
                    }
                    *(float2*)(dstbase + ((size_t)((b*NH + h)*NS + s))*ND + d)
                        = make_float2(oe, oo);
                }
            }
        }
    }
}

// ---------------- Flash attention, tf32 tensor cores -------------------------
// CTA: 128 q-rows, 8 warps (16 q-rows each). 64-key tiles in smem.
// S = Q K^T via mma (Q A-frags in regs), online softmax (fp32),
// P converted to A-frags via lane shuffles (no smem round trip), P V via mma.
#define KSTR 68   // 68 % 32 == 4 : conflict-free for (g, tg) A/Kt pattern
#define VSTR 72   // 72 % 32 == 8 : conflict-free for (tg row, g col) B pattern
__global__ __launch_bounds__(256) void attn_tc()
{
    __shared__ unsigned Ks[64*KSTR];
    __shared__ unsigned Vs[64*VSTR];

    int tid  = threadIdx.x;
    int lane = tid & 31, wid = tid >> 5;
    int g = lane >> 2, tg = lane & 3;
    int bh = blockIdx.y;
    int q0 = blockIdx.x * 128;

    const float* qp = g_q + (size_t)bh * NS * ND;
    const float* kp = g_k + (size_t)bh * NS * ND;
    const float* vp = g_v + (size_t)bh * NS * ND;

    // Q fragments for this warp's 16 rows (rows r0=g, r0+8), all of d=64
    int r0 = q0 + wid*16 + g;
    unsigned qa[8][4];
    #pragma unroll
    for (int ks = 0; ks < 8; ks++) {
        int cc = ks*8 + tg;
        qa[ks][0] = f2tf(qp[(size_t)r0*ND + cc]);
        qa[ks][1] = f2tf(qp[(size_t)(r0+8)*ND + cc]);
        qa[ks][2] = f2tf(qp[(size_t)r0*ND + cc + 4]);
        qa[ks][3] = f2tf(qp[(size_t)(r0+8)*ND + cc + 4]);
    }

    float o[8][4];
    #pragma unroll
    for (int nt = 0; nt < 8; nt++)
        #pragma unroll
        for (int j = 0; j < 4; j++) o[nt][j] = 0.f;
    float m0r = -INFINITY, m1r = -INFINITY, l0 = 0.f, l1 = 0.f;

    int srcA = (lane & ~3) | (tg >> 1);
    int srcB = srcA + 2;
    bool oddl = (tg & 1);

    for (int kt = 0; kt < NS; kt += 64) {
        __syncthreads();
        #pragma unroll
        for (int i = 0; i < 4; i++) {
            int f4 = tid + i*256;           // 0..1023
            int rr = f4 >> 4;               // 0..63
            int cc = (f4 & 15) << 2;        // 0..60
            float4 kv = *(const float4*)(kp + (size_t)(kt+rr)*ND + cc);
            *(uint4*)&Ks[rr*KSTR + cc] =
                make_uint4(f2tf(kv.x), f2tf(kv.y), f2tf(kv.z), f2tf(kv.w));
            float4 vv = *(const float4*)(vp + (size_t)(kt+rr)*ND + cc);
            *(uint4*)&Vs[rr*VSTR + cc] =
                make_uint4(f2tf(vv.x), f2tf(vv.y), f2tf(vv.z), f2tf(vv.w));
        }
        __syncthreads();

        // ---- S = Q K^T (per warp: 16 q-rows x 64 keys) ----
        float s[8][4];
        #pragma unroll
        for (int nt = 0; nt < 8; nt++)
            #pragma unroll
            for (int j = 0; j < 4; j++) s[nt][j] = 0.f;
        #pragma unroll
        for (int ks = 0; ks < 8; ks++) {
            int cidx = ks*8 + tg;
            #pragma unroll
            for (int nt = 0; nt < 8; nt++) {
                unsigned b[2];
                b[0] = Ks[(nt*8+g)*KSTR + cidx];
                b[1] = Ks[(nt*8+g)*KSTR + cidx + 4];
                mma_tf32(s[nt], qa[ks], b);
            }
        }

        // ---- online softmax ----
        float cm0 = -INFINITY, cm1 = -INFINITY;
        #pragma unroll
        for (int nt = 0; nt < 8; nt++) {
            cm0 = fmaxf(cm0, fmaxf(s[nt][0], s[nt][1]));
            cm1 = fmaxf(cm1, fmaxf(s[nt][2], s[nt][3]));
        }
        cm0 = fmaxf(cm0, __shfl_xor_sync(0xffffffffu, cm0, 1));
        cm0 = fmaxf(cm0, __shfl_xor_sync(0xffffffffu, cm0, 2));
        cm1 = fmaxf(cm1, __shfl_xor_sync(0xffffffffu, cm1, 1));
        cm1 = fmaxf(cm1, __shfl_xor_sync(0xffffffffu, cm1, 2));
        float mn0 = fmaxf(m0r, cm0), mn1 = fmaxf(m1r, cm1);
        float corr0 = __expf(m0r - mn0), corr1 = __expf(m1r - mn1);
        m0r = mn0; m1r = mn1;
        l0 *= corr0; l1 *= corr1;

        unsigned up[8][4];
        #pragma unroll
        for (int nt = 0; nt < 8; nt++) {
            float p0 = __expf(s[nt][0] - mn0);
            float p1 = __expf(s[nt][1] - mn0);
            float p2 = __expf(s[nt][2] - mn1);
            float p3 = __expf(s[nt][3] - mn1);
            l0 += p0 + p1;
            l1 += p2 + p3;
            o[nt][0] *= corr0; o[nt][1] *= corr0;
            o[nt][2] *= corr1; o[nt][3] *= corr1;
            up[nt][0] = f2tf(p0); up[nt][1] = f2tf(p1);
            up[nt][2] = f2tf(p2); up[nt][3] = f2tf(p3);
        }

        // ---- O += P V ----
        // P C-fragment (cols 2tg,2tg+1) -> A-fragment (cols tg, tg+4) via shfl.
        #pragma unroll
        for (int ks = 0; ks < 8; ks++) {
            unsigned pa[4], e0, e1;
            e0 = __shfl_sync(0xffffffffu, up[ks][0], srcA);
            e1 = __shfl_sync(0xffffffffu, up[ks][1], srcA);
            pa[0] = oddl ? e1 : e0;
            e0 = __shfl_sync(0xffffffffu, up[ks][2], srcA);
            e1 = __shfl_sync(0xffffffffu, up[ks][3], srcA);
            pa[1] = oddl ? e1 : e0;
            e0 = __shfl_sync(0xffffffffu, up[ks][0], srcB);
            e1 = __shfl_sync(0xffffffffu, up[ks][1], srcB);
            pa[2] = oddl ? e1 : e0;
            e0 = __shfl_sync(0xffffffffu, up[ks][2], srcB);
            e1 = __shfl_sync(0xffffffffu, up[ks][3], srcB);
            pa[3] = oddl ? e1 : e0;
            #pragma unroll
            for (int nt = 0; nt < 8; nt++) {
                unsigned b[2];
                b[0] = Vs[(ks*8+tg)*VSTR + nt*8 + g];
                b[1] = Vs[(ks*8+tg+4)*VSTR + nt*8 + g];
                mma_tf32(o[nt], pa, b);
            }
        }
    }

    // ---- finalize: normalize and write [B,S,H,D] ----
    l0 += __shfl_xor_sync(0xffffffffu, l0, 1);
    l0 += __shfl_xor_sync(0xffffffffu, l0, 2);
    l1 += __shfl_xor_sync(0xffffffffu, l1, 1);
    l1 += __shfl_xor_sync(0xffffffffu, l1, 2);
    float i0 = 1.0f / l0, i1 = 1.0f / l1;

    int b = bh >> 4, h = bh & 15;
    float* dst0 = g_att + (((size_t)(b*NS + r0))  * NH + h) * ND;
    float* dst1 = g_att + (((size_t)(b*NS + r0+8))* NH + h) * ND;
    #pragma unroll
    for (int nt = 0; nt < 8; nt++) {
        int col = nt*8 + 2*tg;
        *(float2*)(dst0 + col) = make_float2(o[nt][0]*i0, o[nt][1]*i0);
        *(float2*)(dst1 + col) = make_float2(o[nt][2]*i1, o[nt][3]*i1);
    }
}

// ------------------------------- launch --------------------------------------
extern "C" void kernel_launch(void* const* d_in, const int* in_sizes, int n_in,
                              void* d_out, int out_size)
{
    const float* query = (const float*)d_in[0];
    const float* key   = (const float*)d_in[1];
    const float* value = (const float*)d_in[2];
    const float* Wq    = (const float*)d_in[3];
    const float* bq    = (const float*)d_in[4];
    const float* Wk    = (const float*)d_in[5];
    const float* bk    = (const float*)d_in[6];
    const float* Wv    = (const float*)d_in[7];
    const float* bv    = (const float*)d_in[8];
    const float* Wo    = (const float*)d_in[9];
    const float* bo    = (const float*)d_in[10];
    float* out = (float*)d_out;

    dim3 ggrid(NE/128, NM/128);   // (8, 32)

    init_invfreq_kernel<<<1, 32>>>();
    gemm_tc<1><<<ggrid, 256>>>(query, Wq, bq, nullptr);
    gemm_tc<2><<<ggrid, 256>>>(key,   Wk, bk, nullptr);
    gemm_tc<3><<<ggrid, 256>>>(value, Wv, bv, nullptr);
    attn_tc<<<dim3(NS/128, NB*NH), 256>>>();
    gemm_tc<0><<<ggrid, 256>>>(nullptr, Wo, bo, out);
}